// round 1
// baseline (speedup 1.0000x reference)
#include <cuda_runtime.h>

#define DN 128        // hidden dim
#define NMAX 100000
#define EMAX 1600000

// ---------------- scratch (no allocations allowed) ----------------
__device__ float g_h[NMAX * DN];      // h_scaled = (x @ W) * dis[row]
__device__ float g_x[NMAX * DN];      // layer output (relu)
__device__ int   g_cnt[NMAX];         // in-degree (edges only)
__device__ float g_dis[NMAX];         // rsqrt(deg) with self loop
__device__ int   g_rowptr[NMAX + 1];
__device__ int   g_fill[NMAX];
__device__ int   g_csr[EMAX];
__device__ int   g_incl[NMAX];        // per-element inclusive scan (chunked)
__device__ int   g_bsum[256];
__device__ int   g_boff[256];

// ---------------- preprocessing kernels ----------------
__global__ void k_init(int n) {
    int i = blockIdx.x * blockDim.x + threadIdx.x;
    if (i < n) { g_cnt[i] = 0; g_fill[i] = 0; }
}

__global__ void k_count(const int* __restrict__ dst, int e) {
    int i = blockIdx.x * blockDim.x + threadIdx.x;
    if (i < e) atomicAdd(&g_cnt[dst[i]], 1);
}

__global__ void k_dis(int n) {
    int i = blockIdx.x * blockDim.x + threadIdx.x;
    if (i < n) g_dis[i] = rsqrtf((float)(g_cnt[i] + 1));  // +1 self loop
}

// scan pass 1: each block scans a 1024-element chunk (256 thr x 4)
__global__ void k_scan1(int n) {
    __shared__ int sh[256];
    int t = threadIdx.x, b = blockIdx.x;
    int base = b * 1024 + t * 4;
    int v[4], s = 0;
#pragma unroll
    for (int i = 0; i < 4; i++) {
        int idx = base + i;
        v[i] = (idx < n) ? g_cnt[idx] : 0;
        s += v[i];
    }
    sh[t] = s; __syncthreads();
    for (int off = 1; off < 256; off <<= 1) {
        int x = (t >= off) ? sh[t - off] : 0;
        __syncthreads();
        sh[t] += x;
        __syncthreads();
    }
    int run = (t == 0) ? 0 : sh[t - 1];
#pragma unroll
    for (int i = 0; i < 4; i++) {
        int idx = base + i;
        run += v[i];
        if (idx < n) g_incl[idx] = run;
    }
    if (t == 255) g_bsum[b] = sh[255];
}

// scan pass 2: single block scans the block sums -> exclusive offsets
__global__ void k_scan2(int nb) {
    __shared__ int sh[256];
    int t = threadIdx.x;
    int v = (t < nb) ? g_bsum[t] : 0;
    sh[t] = v; __syncthreads();
    for (int off = 1; off < 256; off <<= 1) {
        int x = (t >= off) ? sh[t - off] : 0;
        __syncthreads();
        sh[t] += x;
        __syncthreads();
    }
    g_boff[t] = sh[t] - v;   // exclusive
}

// scan pass 3: rowptr[i+1] = inclusive global
__global__ void k_scan3(int n) {
    int i = blockIdx.x * blockDim.x + threadIdx.x;
    if (i < n) {
        g_rowptr[i + 1] = g_incl[i] + g_boff[i >> 10];
        if (i == 0) g_rowptr[0] = 0;
    }
}

__global__ void k_fill(const int* __restrict__ src, const int* __restrict__ dst, int e) {
    int i = blockIdx.x * blockDim.x + threadIdx.x;
    if (i < e) {
        int d = dst[i];
        int pos = g_rowptr[d] + atomicAdd(&g_fill[d], 1);
        g_csr[pos] = src[i];
    }
}

// ---------------- GEMM: h_scaled = (x @ W) * dis[row] ----------------
// block: 256 threads, tile 64 rows x 128 cols, full K=128 in smem.
// smem: x tile 64x128 (32KB) + W 128x128 (64KB) = 96KB dynamic.
__global__ void __launch_bounds__(256)
k_gemm(const float* __restrict__ x, const float* __restrict__ W,
       float* __restrict__ h, int n) {
    extern __shared__ float sm[];
    float* sX = sm;                // [64][128]
    float* sW = sm + 64 * DN;      // [128][128]
    float4* sX4 = (float4*)sX;
    float4* sW4 = (float4*)sW;

    int t = threadIdx.x;
    int row0 = blockIdx.x * 64;

    const float4* W4 = (const float4*)W;
    for (int i = t; i < 128 * 32; i += 256) sW4[i] = W4[i];
    const float4* X4 = (const float4*)x;
    for (int i = t; i < 64 * 32; i += 256) {
        int r = i >> 5, c = i & 31;
        int gr = row0 + r;
        sX4[i] = (gr < n) ? X4[gr * 32 + c] : make_float4(0.f, 0.f, 0.f, 0.f);
    }
    __syncthreads();

    int tx = t & 31;   // column group (4 cols)
    int ty = t >> 5;   // row group (8 rows)
    float4 acc[8];
#pragma unroll
    for (int i = 0; i < 8; i++) acc[i] = make_float4(0.f, 0.f, 0.f, 0.f);

#pragma unroll 4
    for (int k = 0; k < DN; k++) {
        float4 w = sW4[k * 32 + tx];
#pragma unroll
        for (int i = 0; i < 8; i++) {
            float xv = sX[(ty * 8 + i) * DN + k];   // warp-broadcast
            acc[i].x = fmaf(xv, w.x, acc[i].x);
            acc[i].y = fmaf(xv, w.y, acc[i].y);
            acc[i].z = fmaf(xv, w.z, acc[i].z);
            acc[i].w = fmaf(xv, w.w, acc[i].w);
        }
    }

#pragma unroll
    for (int i = 0; i < 8; i++) {
        int r = row0 + ty * 8 + i;
        if (r < n) {
            float s = g_dis[r];
            float4 a = acc[i];
            a.x *= s; a.y *= s; a.z *= s; a.w *= s;
            ((float4*)h)[r * 32 + tx] = a;
        }
    }
}

// ---------------- aggregation: warp per node, gather from CSR ----------------
// out[v] = relu( dis[v] * ( sum_{u->v} h_sc[u] + h_sc[v] ) + b )
__global__ void __launch_bounds__(256)
k_aggregate(const float* __restrict__ h, const float* __restrict__ bias,
            float* __restrict__ out, int n) {
    int warp = (blockIdx.x * blockDim.x + threadIdx.x) >> 5;
    int lane = threadIdx.x & 31;
    if (warp >= n) return;
    int v = warp;

    const float4* h4 = (const float4*)h;
    float4 acc = h4[v * 32 + lane];         // self loop term (already *dis[v])

    int s = g_rowptr[v], e = g_rowptr[v + 1];
    for (int base = s; base < e; base += 32) {
        int idx = (base + lane < e) ? g_csr[base + lane] : 0;
        int m = min(32, e - base);
        for (int j = 0; j < m; j++) {
            int u = __shfl_sync(0xffffffffu, idx, j);
            float4 hv = h4[u * 32 + lane];
            acc.x += hv.x; acc.y += hv.y; acc.z += hv.z; acc.w += hv.w;
        }
    }

    float dv = g_dis[v];
    float4 bb = ((const float4*)bias)[lane];
    acc.x = fmaxf(fmaf(acc.x, dv, bb.x), 0.f);
    acc.y = fmaxf(fmaf(acc.y, dv, bb.y), 0.f);
    acc.z = fmaxf(fmaf(acc.z, dv, bb.z), 0.f);
    acc.w = fmaxf(fmaf(acc.w, dv, bb.w), 0.f);
    ((float4*)out)[v * 32 + lane] = acc;
}

// ---------------- launch ----------------
extern "C" void kernel_launch(void* const* d_in, const int* in_sizes, int n_in,
                              void* d_out, int out_size) {
    const float* x    = (const float*)d_in[0];
    const int*   ei   = (const int*)d_in[1];
    const float* W    = (const float*)d_in[2];
    const float* bias = (const float*)d_in[3];
    float* out = (float*)d_out;

    int n = in_sizes[0] / DN;
    int e = in_sizes[1] / 2;
    const int* src = ei;
    const int* dst = ei + e;

    float *hbuf, *xbuf;
    cudaGetSymbolAddress((void**)&hbuf, g_h);
    cudaGetSymbolAddress((void**)&xbuf, g_x);

    static const int GEMM_SMEM = (64 * DN + DN * DN) * (int)sizeof(float); // 96KB
    cudaFuncSetAttribute(k_gemm, cudaFuncAttributeMaxDynamicSharedMemorySize, GEMM_SMEM);

    int nb_n = (n + 255) / 256;
    int nb_e = (e + 255) / 256;
    int nchunks = (n + 1023) / 1024;

    // preprocessing: degree + CSR by dst
    k_init <<<nb_n, 256>>>(n);
    k_count<<<nb_e, 256>>>(dst, e);
    k_dis  <<<nb_n, 256>>>(n);
    k_scan1<<<nchunks, 256>>>(n);
    k_scan2<<<1, 256>>>(nchunks);
    k_scan3<<<nb_n, 256>>>(n);
    k_fill <<<nb_e, 256>>>(src, dst, e);

    // 3 GCN layers
    const float* cur = x;
    int gemm_blocks = (n + 63) / 64;
    int agg_blocks  = (n * 32 + 255) / 256;   // warp per node, 8 warps/block
    for (int l = 0; l < 3; l++) {
        k_gemm<<<gemm_blocks, 256, GEMM_SMEM>>>(cur, W + l * DN * DN, hbuf, n);
        float* outl = (l == 2) ? out : xbuf;
        k_aggregate<<<agg_blocks, 256>>>(hbuf, bias + l * DN, outl, n);
        cur = xbuf;
    }
}

// round 3
// speedup vs baseline: 1.6603x; 1.6603x over previous
#include <cuda_runtime.h>
#include <cuda_bf16.h>
#include <cstdint>

#define DN 128        // hidden dim
#define NMAX 100000
#define EMAX 1600000

// ---------------- scratch (no allocations allowed) ----------------
__device__ float    g_h[NMAX * DN];      // h_scaled = (x @ W) * dis[row]
__device__ float    g_x[NMAX * DN];      // layer output (relu)
__device__ int      g_cnt[NMAX];
__device__ float    g_dis[NMAX];
__device__ int      g_rowptr[NMAX + 1];
__device__ int      g_fill[NMAX];
__device__ int      g_csr[EMAX];
__device__ int      g_incl[NMAX];
__device__ int      g_bsum[256];
__device__ int      g_boff[256];
// W^T bf16 hi/lo images: Bt[n][k] pairs, [3 layers][128 rows][64 u32]
__device__ uint32_t g_wthi[3 * 8192];
__device__ uint32_t g_wtlo[3 * 8192];

// pack (a -> low bf16, b -> high bf16)
__device__ __forceinline__ uint32_t cvt2(float a, float b) {
    uint32_t r;
    asm("cvt.rn.satfinite.bf16x2.f32 %0, %1, %2;" : "=r"(r) : "f"(b), "f"(a));
    return r;
}

__device__ __forceinline__ void mma_bf16(float* d, const uint32_t* a, const uint32_t* b) {
    asm volatile(
        "mma.sync.aligned.m16n8k16.row.col.f32.bf16.bf16.f32 "
        "{%0,%1,%2,%3}, {%4,%5,%6,%7}, {%8,%9}, {%0,%1,%2,%3};"
        : "+f"(d[0]), "+f"(d[1]), "+f"(d[2]), "+f"(d[3])
        : "r"(a[0]), "r"(a[1]), "r"(a[2]), "r"(a[3]), "r"(b[0]), "r"(b[1]));
}

// ---------------- preprocessing kernels ----------------
__global__ void k_init(int n) {
    int i = blockIdx.x * blockDim.x + threadIdx.x;
    if (i < n) { g_cnt[i] = 0; g_fill[i] = 0; }
}
__global__ void k_count(const int* __restrict__ dst, int e) {
    int i = blockIdx.x * blockDim.x + threadIdx.x;
    if (i < e) atomicAdd(&g_cnt[dst[i]], 1);
}
__global__ void k_dis(int n) {
    int i = blockIdx.x * blockDim.x + threadIdx.x;
    if (i < n) g_dis[i] = rsqrtf((float)(g_cnt[i] + 1));
}
__global__ void k_scan1(int n) {
    __shared__ int sh[256];
    int t = threadIdx.x, b = blockIdx.x;
    int base = b * 1024 + t * 4;
    int v[4], s = 0;
#pragma unroll
    for (int i = 0; i < 4; i++) {
        int idx = base + i;
        v[i] = (idx < n) ? g_cnt[idx] : 0;
        s += v[i];
    }
    sh[t] = s; __syncthreads();
    for (int off = 1; off < 256; off <<= 1) {
        int x = (t >= off) ? sh[t - off] : 0;
        __syncthreads(); sh[t] += x; __syncthreads();
    }
    int run = (t == 0) ? 0 : sh[t - 1];
#pragma unroll
    for (int i = 0; i < 4; i++) {
        int idx = base + i;
        run += v[i];
        if (idx < n) g_incl[idx] = run;
    }
    if (t == 255) g_bsum[b] = sh[255];
}
__global__ void k_scan2(int nb) {
    __shared__ int sh[256];
    int t = threadIdx.x;
    int v = (t < nb) ? g_bsum[t] : 0;
    sh[t] = v; __syncthreads();
    for (int off = 1; off < 256; off <<= 1) {
        int x = (t >= off) ? sh[t - off] : 0;
        __syncthreads(); sh[t] += x; __syncthreads();
    }
    g_boff[t] = sh[t] - v;
}
__global__ void k_scan3(int n) {
    int i = blockIdx.x * blockDim.x + threadIdx.x;
    if (i < n) {
        g_rowptr[i + 1] = g_incl[i] + g_boff[i >> 10];
        if (i == 0) g_rowptr[0] = 0;
    }
}
__global__ void k_fill(const int* __restrict__ src, const int* __restrict__ dst, int e) {
    int i = blockIdx.x * blockDim.x + threadIdx.x;
    if (i < e) {
        int d = dst[i];
        int pos = g_rowptr[d] + atomicAdd(&g_fill[d], 1);
        g_csr[pos] = src[i];
    }
}

// ---------------- W split: transposed bf16 hi/lo images Bt[n][k] ----------------
__global__ void k_wsplit(const float* __restrict__ W) {
    int idx = blockIdx.x * blockDim.x + threadIdx.x;   // 3*128*64
    if (idx >= 3 * 128 * 64) return;
    int l  = idx >> 13;
    int r  = idx & 8191;
    int nn = r >> 6;        // output col
    int kk = r & 63;        // k pair
    int k  = 2 * kk;
    float a = W[l * 16384 + k * 128 + nn];
    float b = W[l * 16384 + (k + 1) * 128 + nn];
    uint32_t whi = cvt2(a, b);
    float fa = __uint_as_float(whi << 16);
    float fb = __uint_as_float(whi & 0xffff0000u);
    uint32_t wlo = cvt2(a - fa, b - fb);
    g_wthi[l * 8192 + nn * 64 + kk] = whi;
    g_wtlo[l * 8192 + nn * 64 + kk] = wlo;
}

// ---------------- HMMA GEMM: h = (x @ W) * dis[row] ----------------
// CTA: 256 thr (8 warps), tile 128x128, K=128 fully resident.
// bf16 3-split: Ahi*Bhi + Ahi*Blo + Alo*Bhi, fp32 accum in regs.
// smem rows padded to 68 u32 (272B) -> conflict-free quad b32 loads.
#define ASTRIDE 68
#define TILE_U32 (128 * ASTRIDE)          // 8704 u32 per image
#define GEMM_SMEM (4 * TILE_U32 * 4)      // 139264 B

__global__ void __launch_bounds__(256, 1)
k_gemm_mma(const float* __restrict__ x, int layer, float* __restrict__ h, int n) {
    extern __shared__ uint32_t sm[];
    uint32_t* sAhi = sm;
    uint32_t* sAlo = sm + TILE_U32;
    uint32_t* sBhi = sm + 2 * TILE_U32;
    uint32_t* sBlo = sm + 3 * TILE_U32;

    int t = threadIdx.x;
    int wid = t >> 5, lane = t & 31;
    int g = lane >> 2, t4 = lane & 3;     // mma fragment coords
    int warpM = wid & 3;                  // 4 warps along M (32 rows each)
    int warpN = wid >> 2;                 // 2 warps along N (64 cols each)
    int row0 = blockIdx.x * 128;

    // ---- load B images (hi/lo): 128 rows x 16 uint4 each ----
    {
        const uint4* srcH = (const uint4*)(g_wthi + layer * 8192);
        const uint4* srcL = (const uint4*)(g_wtlo + layer * 8192);
#pragma unroll
        for (int i = t; i < 2048; i += 256) {
            int r = i >> 4, q = i & 15;
            uint4 vh = srcH[i];
            uint4 vl = srcL[i];
            *(uint4*)(sBhi + r * ASTRIDE + q * 4) = vh;
            *(uint4*)(sBlo + r * ASTRIDE + q * 4) = vl;
        }
    }
    // ---- load + split A tile: 128 rows x 128 cols fp32 ----
    {
        const float4* X4 = (const float4*)x;
#pragma unroll
        for (int it = 0; it < 16; it++) {
            int idx = t + it * 256;       // [0, 4096)
            int r = idx >> 5, q = idx & 31;
            int gr = row0 + r;
            float4 v = (gr < n) ? X4[gr * 32 + q] : make_float4(0.f, 0.f, 0.f, 0.f);
            uint32_t w0 = cvt2(v.x, v.y);
            uint32_t w1 = cvt2(v.z, v.w);
            float f0 = __uint_as_float(w0 << 16);
            float f1 = __uint_as_float(w0 & 0xffff0000u);
            float f2 = __uint_as_float(w1 << 16);
            float f3 = __uint_as_float(w1 & 0xffff0000u);
            uint32_t u0 = cvt2(v.x - f0, v.y - f1);
            uint32_t u1 = cvt2(v.z - f2, v.w - f3);
            *(uint2*)(sAhi + r * ASTRIDE + 2 * q) = make_uint2(w0, w1);
            *(uint2*)(sAlo + r * ASTRIDE + 2 * q) = make_uint2(u0, u1);
        }
    }
    __syncthreads();

    float d[2][8][4];
#pragma unroll
    for (int mt = 0; mt < 2; mt++)
#pragma unroll
        for (int nt = 0; nt < 8; nt++)
#pragma unroll
            for (int i = 0; i < 4; i++) d[mt][nt][i] = 0.f;

#pragma unroll
    for (int p = 0; p < 3; p++) {
        const uint32_t* pa = (p == 2) ? sAlo : sAhi;
        const uint32_t* pb = (p == 1) ? sBlo : sBhi;
#pragma unroll
        for (int ks = 0; ks < 8; ks++) {
            int kb = ks * 8;
            uint32_t a[2][4];
#pragma unroll
            for (int mt = 0; mt < 2; mt++) {
                int r = warpM * 32 + mt * 16 + g;
                a[mt][0] = pa[r * ASTRIDE + kb + t4];
                a[mt][1] = pa[(r + 8) * ASTRIDE + kb + t4];
                a[mt][2] = pa[r * ASTRIDE + kb + t4 + 4];
                a[mt][3] = pa[(r + 8) * ASTRIDE + kb + t4 + 4];
            }
            uint32_t b[8][2];
#pragma unroll
            for (int nt = 0; nt < 8; nt++) {
                int c = warpN * 64 + nt * 8 + g;
                b[nt][0] = pb[c * ASTRIDE + kb + t4];
                b[nt][1] = pb[c * ASTRIDE + kb + t4 + 4];
            }
#pragma unroll
            for (int mt = 0; mt < 2; mt++)
#pragma unroll
                for (int nt = 0; nt < 8; nt++)
                    mma_bf16(d[mt][nt], a[mt], b[nt]);
        }
    }

    // ---- epilogue: scale by dis[row], store fp32 ----
#pragma unroll
    for (int mt = 0; mt < 2; mt++) {
        int r1 = row0 + warpM * 32 + mt * 16 + g;
        int r2 = r1 + 8;
        float s1 = (r1 < n) ? g_dis[r1] : 0.f;
        float s2 = (r2 < n) ? g_dis[r2] : 0.f;
#pragma unroll
        for (int nt = 0; nt < 8; nt++) {
            int c = warpN * 64 + nt * 8 + t4 * 2;
            if (r1 < n) {
                float2 o = make_float2(d[mt][nt][0] * s1, d[mt][nt][1] * s1);
                *(float2*)(h + r1 * DN + c) = o;
            }
            if (r2 < n) {
                float2 o = make_float2(d[mt][nt][2] * s2, d[mt][nt][3] * s2);
                *(float2*)(h + r2 * DN + c) = o;
            }
        }
    }
}

// ---------------- aggregation: warp per node, gather from CSR ----------------
__global__ void __launch_bounds__(256)
k_aggregate(const float* __restrict__ h, const float* __restrict__ bias,
            float* __restrict__ out, int n) {
    int warp = (blockIdx.x * blockDim.x + threadIdx.x) >> 5;
    int lane = threadIdx.x & 31;
    if (warp >= n) return;
    int v = warp;

    const float4* __restrict__ h4 = (const float4*)h;
    float4 a0 = h4[v * 32 + lane];   // self loop (already *dis[v])
    float4 a1 = make_float4(0.f, 0.f, 0.f, 0.f);

    int s = g_rowptr[v], e = g_rowptr[v + 1];
    for (int base = s; base < e; base += 32) {
        int rem = e - base;
        int m = rem < 32 ? rem : 32;
        int idx = (lane < m) ? g_csr[base + lane] : 0;
        int j = 0;
        for (; j + 4 <= m; j += 4) {
            int u0 = __shfl_sync(0xffffffffu, idx, j);
            int u1 = __shfl_sync(0xffffffffu, idx, j + 1);
            int u2 = __shfl_sync(0xffffffffu, idx, j + 2);
            int u3 = __shfl_sync(0xffffffffu, idx, j + 3);
            float4 f0 = h4[u0 * 32 + lane];
            float4 f1 = h4[u1 * 32 + lane];
            float4 f2 = h4[u2 * 32 + lane];
            float4 f3 = h4[u3 * 32 + lane];
            a0.x += f0.x; a0.y += f0.y; a0.z += f0.z; a0.w += f0.w;
            a1.x += f1.x; a1.y += f1.y; a1.z += f1.z; a1.w += f1.w;
            a0.x += f2.x; a0.y += f2.y; a0.z += f2.z; a0.w += f2.w;
            a1.x += f3.x; a1.y += f3.y; a1.z += f3.z; a1.w += f3.w;
        }
        for (; j < m; j++) {
            int u = __shfl_sync(0xffffffffu, idx, j);
            float4 f = h4[u * 32 + lane];
            a0.x += f.x; a0.y += f.y; a0.z += f.z; a0.w += f.w;
        }
    }

    float dv = g_dis[v];
    float4 bb = ((const float4*)bias)[lane];
    float4 o;
    o.x = fmaxf(fmaf(a0.x + a1.x, dv, bb.x), 0.f);
    o.y = fmaxf(fmaf(a0.y + a1.y, dv, bb.y), 0.f);
    o.z = fmaxf(fmaf(a0.z + a1.z, dv, bb.z), 0.f);
    o.w = fmaxf(fmaf(a0.w + a1.w, dv, bb.w), 0.f);
    ((float4*)out)[v * 32 + lane] = o;
}

// ---------------- launch ----------------
extern "C" void kernel_launch(void* const* d_in, const int* in_sizes, int n_in,
                              void* d_out, int out_size) {
    const float* x    = (const float*)d_in[0];
    const int*   ei   = (const int*)d_in[1];
    const float* W    = (const float*)d_in[2];
    const float* bias = (const float*)d_in[3];
    float* out = (float*)d_out;

    int n = in_sizes[0] / DN;
    int e = in_sizes[1] / 2;
    const int* src = ei;
    const int* dst = ei + e;

    float *hbuf, *xbuf;
    cudaGetSymbolAddress((void**)&hbuf, g_h);
    cudaGetSymbolAddress((void**)&xbuf, g_x);

    cudaFuncSetAttribute(k_gemm_mma, cudaFuncAttributeMaxDynamicSharedMemorySize, GEMM_SMEM);

    int nb_n = (n + 255) / 256;
    int nb_e = (e + 255) / 256;
    int nchunks = (n + 1023) / 1024;

    // preprocessing: degree + CSR by dst + W split images
    k_init  <<<nb_n, 256>>>(n);
    k_count <<<nb_e, 256>>>(dst, e);
    k_dis   <<<nb_n, 256>>>(n);
    k_scan1 <<<nchunks, 256>>>(n);
    k_scan2 <<<1, 256>>>(nchunks);
    k_scan3 <<<nb_n, 256>>>(n);
    k_fill  <<<nb_e, 256>>>(src, dst, e);
    k_wsplit<<<(3 * 128 * 64 + 255) / 256, 256>>>(W);

    // 3 GCN layers
    const float* cur = x;
    int gemm_blocks = (n + 127) / 128;
    int agg_blocks  = (n * 32 + 255) / 256;
    for (int l = 0; l < 3; l++) {
        k_gemm_mma<<<gemm_blocks, 256, GEMM_SMEM>>>(cur, l, hbuf, n);
        float* outl = (l == 2) ? out : xbuf;
        k_aggregate<<<agg_blocks, 256>>>(hbuf, bias + l * DN, outl, n);
        cur = xbuf;
    }
}

// round 5
// speedup vs baseline: 1.9979x; 1.2034x over previous
#include <cuda_runtime.h>
#include <cuda_bf16.h>
#include <cuda_fp16.h>
#include <cstdint>

#define DN 128        // hidden dim
#define NMAX 100000
#define EMAX 1600000

// ---------------- scratch (no allocations allowed) ----------------
__device__ uint32_t g_h[NMAX * 64];      // h_scaled as fp16x2: 64 u32 per row
__device__ float    g_x[NMAX * DN];      // layer output (relu), fp32
__device__ int      g_cnt[NMAX];
__device__ float    g_dis[NMAX];
__device__ int      g_rowptr[NMAX + 1];
__device__ int      g_fill[NMAX];
__device__ int      g_csr[EMAX];
__device__ int      g_incl[NMAX];
__device__ int      g_bsum[256];
__device__ int      g_boff[256];
// W^T bf16 hi/lo images: Bt[n][k] pairs, [3 layers][128 rows][64 u32]
__device__ uint32_t g_wthi[3 * 8192];
__device__ uint32_t g_wtlo[3 * 8192];

// pack (a -> low bf16, b -> high bf16)
__device__ __forceinline__ uint32_t cvt2(float a, float b) {
    uint32_t r;
    asm("cvt.rn.satfinite.bf16x2.f32 %0, %1, %2;" : "=r"(r) : "f"(b), "f"(a));
    return r;
}
__device__ __forceinline__ uint32_t smem_u32(const void* p) {
    uint32_t a;
    asm("{ .reg .u64 t; cvta.to.shared.u64 t, %1; cvt.u32.u64 %0, t; }" : "=r"(a) : "l"(p));
    return a;
}
__device__ __forceinline__ void mma_bf16(float* d, const uint32_t* a, const uint32_t* b) {
    asm volatile(
        "mma.sync.aligned.m16n8k16.row.col.f32.bf16.bf16.f32 "
        "{%0,%1,%2,%3}, {%4,%5,%6,%7}, {%8,%9}, {%0,%1,%2,%3};"
        : "+f"(d[0]), "+f"(d[1]), "+f"(d[2]), "+f"(d[3])
        : "r"(a[0]), "r"(a[1]), "r"(a[2]), "r"(a[3]), "r"(b[0]), "r"(b[1]));
}
#define LDSM_X4(r0, r1, r2, r3, addr) \
    asm volatile("ldmatrix.sync.aligned.m8n8.x4.shared.b16 {%0,%1,%2,%3}, [%4];" \
        : "=r"(r0), "=r"(r1), "=r"(r2), "=r"(r3) : "r"(addr))

// ---------------- preprocessing kernels ----------------
__global__ void k_init(int n) {
    int i = blockIdx.x * blockDim.x + threadIdx.x;
    if (i < n) { g_cnt[i] = 0; g_fill[i] = 0; }
}
__global__ void k_count(const int* __restrict__ dst, int e) {
    int i = blockIdx.x * blockDim.x + threadIdx.x;
    if (i < e) atomicAdd(&g_cnt[dst[i]], 1);
}
__global__ void k_dis(int n) {
    int i = blockIdx.x * blockDim.x + threadIdx.x;
    if (i < n) g_dis[i] = rsqrtf((float)(g_cnt[i] + 1));
}
__global__ void k_scan1(int n) {
    __shared__ int sh[256];
    int t = threadIdx.x, b = blockIdx.x;
    int base = b * 1024 + t * 4;
    int v[4], s = 0;
#pragma unroll
    for (int i = 0; i < 4; i++) {
        int idx = base + i;
        v[i] = (idx < n) ? g_cnt[idx] : 0;
        s += v[i];
    }
    sh[t] = s; __syncthreads();
    for (int off = 1; off < 256; off <<= 1) {
        int x = (t >= off) ? sh[t - off] : 0;
        __syncthreads(); sh[t] += x; __syncthreads();
    }
    int run = (t == 0) ? 0 : sh[t - 1];
#pragma unroll
    for (int i = 0; i < 4; i++) {
        int idx = base + i;
        run += v[i];
        if (idx < n) g_incl[idx] = run;
    }
    if (t == 255) g_bsum[b] = sh[255];
}
__global__ void k_scan2(int nb) {
    __shared__ int sh[256];
    int t = threadIdx.x;
    int v = (t < nb) ? g_bsum[t] : 0;
    sh[t] = v; __syncthreads();
    for (int off = 1; off < 256; off <<= 1) {
        int x = (t >= off) ? sh[t - off] : 0;
        __syncthreads(); sh[t] += x; __syncthreads();
    }
    g_boff[t] = sh[t] - v;
}
__global__ void k_scan3(int n) {
    int i = blockIdx.x * blockDim.x + threadIdx.x;
    if (i < n) {
        g_rowptr[i + 1] = g_incl[i] + g_boff[i >> 10];
        if (i == 0) g_rowptr[0] = 0;
    }
}
__global__ void k_fill(const int* __restrict__ src, const int* __restrict__ dst, int e) {
    int i = blockIdx.x * blockDim.x + threadIdx.x;
    if (i < e) {
        int d = dst[i];
        int pos = g_rowptr[d] + atomicAdd(&g_fill[d], 1);
        g_csr[pos] = src[i];
    }
}

// ---------------- W split: transposed bf16 hi/lo images Bt[n][k] ----------------
__global__ void k_wsplit(const float* __restrict__ W) {
    int idx = blockIdx.x * blockDim.x + threadIdx.x;   // 3*128*64
    if (idx >= 3 * 128 * 64) return;
    int l  = idx >> 13;
    int r  = idx & 8191;
    int nn = r >> 6;        // output col
    int kk = r & 63;        // k pair
    int k  = 2 * kk;
    float a = W[l * 16384 + k * 128 + nn];
    float b = W[l * 16384 + (k + 1) * 128 + nn];
    uint32_t whi = cvt2(a, b);
    float fa = __uint_as_float(whi << 16);
    float fb = __uint_as_float(whi & 0xffff0000u);
    uint32_t wlo = cvt2(a - fa, b - fb);
    g_wthi[l * 8192 + nn * 64 + kk] = whi;
    g_wtlo[l * 8192 + nn * 64 + kk] = wlo;
}

// ---------------- HMMA GEMM: h(fp16) = (x @ W) * dis[row] ----------------
// CTA: 256 thr (8 warps), tile 128x128, K=128 fully resident.
// bf16 3-split: Ahi*Bhi + Ahi*Blo + Alo*Bhi, fp32 accum in regs, ldmatrix frags.
#define ASTRIDE 68
#define TILE_U32 (128 * ASTRIDE)          // 8704 u32 per image
#define GEMM_SMEM (4 * TILE_U32 * 4)      // 139264 B

__global__ void __launch_bounds__(256, 1)
k_gemm_mma(const float* __restrict__ x, int layer, uint32_t* __restrict__ h, int n) {
    extern __shared__ uint32_t sm[];
    uint32_t* sAhi = sm;
    uint32_t* sAlo = sm + TILE_U32;
    uint32_t* sBhi = sm + 2 * TILE_U32;
    uint32_t* sBlo = sm + 3 * TILE_U32;

    int t = threadIdx.x;
    int wid = t >> 5, lane = t & 31;
    int g = lane >> 2, t4 = lane & 3;     // mma fragment coords
    int warpM = wid & 3;                  // 4 warps along M (32 rows each)
    int warpN = wid >> 2;                 // 2 warps along N (64 cols each)
    int row0 = blockIdx.x * 128;

    // ---- load B images (hi/lo) ----
    {
        const uint4* srcH = (const uint4*)(g_wthi + layer * 8192);
        const uint4* srcL = (const uint4*)(g_wtlo + layer * 8192);
#pragma unroll
        for (int i = t; i < 2048; i += 256) {
            int r = i >> 4, q = i & 15;
            uint4 vh = srcH[i];
            uint4 vl = srcL[i];
            *(uint4*)(sBhi + r * ASTRIDE + q * 4) = vh;
            *(uint4*)(sBlo + r * ASTRIDE + q * 4) = vl;
        }
    }
    // ---- load + split A tile: 128 rows x 128 cols fp32 ----
    {
        const float4* X4 = (const float4*)x;
#pragma unroll
        for (int it = 0; it < 16; it++) {
            int idx = t + it * 256;       // [0, 4096)
            int r = idx >> 5, q = idx & 31;
            int gr = row0 + r;
            float4 v = (gr < n) ? X4[gr * 32 + q] : make_float4(0.f, 0.f, 0.f, 0.f);
            uint32_t w0 = cvt2(v.x, v.y);
            uint32_t w1 = cvt2(v.z, v.w);
            float f0 = __uint_as_float(w0 << 16);
            float f1 = __uint_as_float(w0 & 0xffff0000u);
            float f2 = __uint_as_float(w1 << 16);
            float f3 = __uint_as_float(w1 & 0xffff0000u);
            uint32_t u0 = cvt2(v.x - f0, v.y - f1);
            uint32_t u1 = cvt2(v.z - f2, v.w - f3);
            *(uint2*)(sAhi + r * ASTRIDE + 2 * q) = make_uint2(w0, w1);
            *(uint2*)(sAlo + r * ASTRIDE + 2 * q) = make_uint2(u0, u1);
        }
    }
    __syncthreads();

    // ldmatrix lane-address offsets (bytes, relative to image base)
    int lrow = lane & 7;
    // A: lanes 0-7 m0(rows, k0), 8-15 m1(rows+8, k0), 16-23 m2(rows, k8), 24-31 m3(rows+8, k8)
    uint32_t aoff = (uint32_t)(((warpM * 32 + lrow + (((lane >> 3) & 1) << 3)) * ASTRIDE
                                + ((lane >> 4) << 2)) * 4);
    // B: lanes 0-7 nt rows k0, 8-15 nt rows k8, 16-23 nt+8 rows k0, 24-31 nt+8 rows k8
    uint32_t boff = (uint32_t)(((warpN * 64 + lrow + ((lane >> 4) << 3)) * ASTRIDE
                                + (((lane >> 3) & 1) << 2)) * 4);
    uint32_t smem_base = smem_u32(sm);

    float d[2][8][4];
#pragma unroll
    for (int mt = 0; mt < 2; mt++)
#pragma unroll
        for (int nt = 0; nt < 8; nt++)
#pragma unroll
            for (int i = 0; i < 4; i++) d[mt][nt][i] = 0.f;

#pragma unroll
    for (int p = 0; p < 3; p++) {
        uint32_t abase = smem_base + (p == 2 ? TILE_U32 * 4u : 0u) + aoff;
        uint32_t bbase = smem_base + (p == 1 ? TILE_U32 * 12u : TILE_U32 * 8u) + boff;
#pragma unroll
        for (int ks = 0; ks < 8; ks++) {
            uint32_t kbyte = (uint32_t)(ks * 32);   // 8 u32 per kstep
            uint32_t a[2][4];
            LDSM_X4(a[0][0], a[0][1], a[0][2], a[0][3], abase + kbyte);
            LDSM_X4(a[1][0], a[1][1], a[1][2], a[1][3], abase + kbyte + 16u * ASTRIDE * 4u);
            uint32_t b[8][2];
#pragma unroll
            for (int ntp = 0; ntp < 4; ntp++) {
                LDSM_X4(b[2 * ntp][0], b[2 * ntp][1], b[2 * ntp + 1][0], b[2 * ntp + 1][1],
                        bbase + kbyte + (uint32_t)(ntp * 16 * ASTRIDE * 4));
            }
#pragma unroll
            for (int mt = 0; mt < 2; mt++)
#pragma unroll
                for (int nt = 0; nt < 8; nt++)
                    mma_bf16(d[mt][nt], a[mt], b[nt]);
        }
    }

    // ---- epilogue: scale by dis[row], store fp16x2 ----
#pragma unroll
    for (int mt = 0; mt < 2; mt++) {
        int r1 = row0 + warpM * 32 + mt * 16 + g;
        int r2 = r1 + 8;
        float s1 = (r1 < n) ? g_dis[r1] : 0.f;
        float s2 = (r2 < n) ? g_dis[r2] : 0.f;
#pragma unroll
        for (int nt = 0; nt < 8; nt++) {
            int cu = warpN * 32 + nt * 4 + t4;   // u32 (half2) column index
            if (r1 < n) {
                __half2 o = __floats2half2_rn(d[mt][nt][0] * s1, d[mt][nt][1] * s1);
                h[r1 * 64 + cu] = *(uint32_t*)&o;
            }
            if (r2 < n) {
                __half2 o = __floats2half2_rn(d[mt][nt][2] * s2, d[mt][nt][3] * s2);
                h[r2 * 64 + cu] = *(uint32_t*)&o;
            }
        }
    }
}

// ---------------- aggregation: warp per node, fp16 gather, fp32 accum ----------------
__device__ __forceinline__ void acc2(float2& a0, float2& a1, uint2 q) {
    float2 f0 = __half22float2(*(__half2*)&q.x);
    float2 f1 = __half22float2(*(__half2*)&q.y);
    a0.x += f0.x; a0.y += f0.y; a1.x += f1.x; a1.y += f1.y;
}

__global__ void __launch_bounds__(256)
k_aggregate(const uint32_t* __restrict__ h, const float* __restrict__ bias,
            float* __restrict__ out, int n) {
    int warp = (blockIdx.x * blockDim.x + threadIdx.x) >> 5;
    int lane = threadIdx.x & 31;
    if (warp >= n) return;
    int v = warp;

    const uint2* __restrict__ h2 = (const uint2*)h;   // 32 uint2 per row (4 halfs/lane)
    float2 a0 = make_float2(0.f, 0.f), a1 = make_float2(0.f, 0.f);
    float2 c0 = make_float2(0.f, 0.f), c1 = make_float2(0.f, 0.f);
    acc2(a0, a1, h2[v * 32 + lane]);                   // self loop (already *dis[v])

    int s = g_rowptr[v], e = g_rowptr[v + 1];
    for (int base = s; base < e; base += 32) {
        int rem = e - base;
        int m = rem < 32 ? rem : 32;
        int idx = (lane < m) ? g_csr[base + lane] : 0;
        int j = 0;
        for (; j + 4 <= m; j += 4) {
            int u0 = __shfl_sync(0xffffffffu, idx, j);
            int u1 = __shfl_sync(0xffffffffu, idx, j + 1);
            int u2 = __shfl_sync(0xffffffffu, idx, j + 2);
            int u3 = __shfl_sync(0xffffffffu, idx, j + 3);
            uint2 q0 = h2[u0 * 32 + lane];
            uint2 q1 = h2[u1 * 32 + lane];
            uint2 q2 = h2[u2 * 32 + lane];
            uint2 q3 = h2[u3 * 32 + lane];
            acc2(a0, a1, q0);
            acc2(c0, c1, q1);
            acc2(a0, a1, q2);
            acc2(c0, c1, q3);
        }
        for (; j < m; j++) {
            int u = __shfl_sync(0xffffffffu, idx, j);
            acc2(a0, a1, h2[u * 32 + lane]);
        }
    }

    float dv = g_dis[v];
    float4 bb = ((const float4*)bias)[lane];
    float4 o;
    o.x = fmaxf(fmaf(a0.x + c0.x, dv, bb.x), 0.f);
    o.y = fmaxf(fmaf(a0.y + c0.y, dv, bb.y), 0.f);
    o.z = fmaxf(fmaf(a1.x + c1.x, dv, bb.z), 0.f);
    o.w = fmaxf(fmaf(a1.y + c1.y, dv, bb.w), 0.f);
    ((float4*)out)[v * 32 + lane] = o;
}

// ---------------- launch ----------------
extern "C" void kernel_launch(void* const* d_in, const int* in_sizes, int n_in,
                              void* d_out, int out_size) {
    const float* x    = (const float*)d_in[0];
    const int*   ei   = (const int*)d_in[1];
    const float* W    = (const float*)d_in[2];
    const float* bias = (const float*)d_in[3];
    float* out = (float*)d_out;

    int n = in_sizes[0] / DN;
    int e = in_sizes[1] / 2;
    const int* src = ei;
    const int* dst = ei + e;

    uint32_t* hbuf;
    float* xbuf;
    cudaGetSymbolAddress((void**)&hbuf, g_h);
    cudaGetSymbolAddress((void**)&xbuf, g_x);

    cudaFuncSetAttribute(k_gemm_mma, cudaFuncAttributeMaxDynamicSharedMemorySize, GEMM_SMEM);

    int nb_n = (n + 255) / 256;
    int nb_e = (e + 255) / 256;
    int nchunks = (n + 1023) / 1024;

    // preprocessing: degree + CSR by dst + W split images
    k_init  <<<nb_n, 256>>>(n);
    k_count <<<nb_e, 256>>>(dst, e);
    k_dis   <<<nb_n, 256>>>(n);
    k_scan1 <<<nchunks, 256>>>(n);
    k_scan2 <<<1, 256>>>(nchunks);
    k_scan3 <<<nb_n, 256>>>(n);
    k_fill  <<<nb_e, 256>>>(src, dst, e);
    k_wsplit<<<(3 * 128 * 64 + 255) / 256, 256>>>(W);

    // 3 GCN layers
    const float* cur = x;
    int gemm_blocks = (n + 127) / 128;
    int agg_blocks  = (n * 32 + 255) / 256;
    for (int l = 0; l < 3; l++) {
        k_gemm_mma<<<gemm_blocks, 256, GEMM_SMEM>>>(cur, l, hbuf, n);
        float* outl = (l == 2) ? out : xbuf;
        k_aggregate<<<agg_blocks, 256>>>(hbuf, bias + l * DN, outl, n);
        cur = xbuf;
    }
}

// round 6
// speedup vs baseline: 2.2459x; 1.1241x over previous
#include <cuda_runtime.h>
#include <cuda_bf16.h>
#include <cuda_fp16.h>
#include <cstdint>

#define DN 128        // hidden dim
#define NMAX 100000
#define EMAX 1600000

// ---------------- scratch (no allocations allowed) ----------------
__device__ uint32_t g_h[NMAX * 64];      // h_scaled as fp16x2: 64 u32 per row
__device__ uint32_t g_x[NMAX * 64];      // layer output (relu) as fp16x2
__device__ int      g_cnt[NMAX];
__device__ float    g_dis[NMAX];
__device__ int      g_rowptr[NMAX + 1];
__device__ int      g_fill[NMAX];
__device__ int      g_csr[EMAX];
__device__ int      g_incl[NMAX];
__device__ int      g_bsum[256];
__device__ int      g_boff[256];
// W^T fp16 hi/lo images: Bt[n][k] pairs, [3 layers][128 rows][64 u32]
__device__ uint32_t g_wthi[3 * 8192];
__device__ uint32_t g_wtlo[3 * 8192];

__device__ __forceinline__ uint32_t pack_h2(float a, float b) {
    __half2 h = __floats2half2_rn(a, b);
    return *(uint32_t*)&h;
}
__device__ __forceinline__ uint32_t smem_u32(const void* p) {
    uint32_t a;
    asm("{ .reg .u64 t; cvta.to.shared.u64 t, %1; cvt.u32.u64 %0, t; }" : "=r"(a) : "l"(p));
    return a;
}
__device__ __forceinline__ void mma_f16(float* d, const uint32_t* a, const uint32_t* b) {
    asm volatile(
        "mma.sync.aligned.m16n8k16.row.col.f32.f16.f16.f32 "
        "{%0,%1,%2,%3}, {%4,%5,%6,%7}, {%8,%9}, {%0,%1,%2,%3};"
        : "+f"(d[0]), "+f"(d[1]), "+f"(d[2]), "+f"(d[3])
        : "r"(a[0]), "r"(a[1]), "r"(a[2]), "r"(a[3]), "r"(b[0]), "r"(b[1]));
}
#define LDSM_X4(r0, r1, r2, r3, addr) \
    asm volatile("ldmatrix.sync.aligned.m8n8.x4.shared.b16 {%0,%1,%2,%3}, [%4];" \
        : "=r"(r0), "=r"(r1), "=r"(r2), "=r"(r3) : "r"(addr))

// ---------------- preprocessing kernels ----------------
__global__ void k_init(int n) {
    int i = blockIdx.x * blockDim.x + threadIdx.x;
    if (i < n) { g_cnt[i] = 0; g_fill[i] = 0; }
}
__global__ void k_count(const int* __restrict__ dst, int e) {
    int i = blockIdx.x * blockDim.x + threadIdx.x;
    if (i < e) atomicAdd(&g_cnt[dst[i]], 1);
}
// scan pass 1 (also computes dis = rsqrt(deg+1))
__global__ void k_scan1(int n) {
    __shared__ int sh[256];
    int t = threadIdx.x, b = blockIdx.x;
    int base = b * 1024 + t * 4;
    int v[4], s = 0;
#pragma unroll
    for (int i = 0; i < 4; i++) {
        int idx = base + i;
        v[i] = (idx < n) ? g_cnt[idx] : 0;
        if (idx < n) g_dis[idx] = rsqrtf((float)(v[i] + 1));
        s += v[i];
    }
    sh[t] = s; __syncthreads();
    for (int off = 1; off < 256; off <<= 1) {
        int x = (t >= off) ? sh[t - off] : 0;
        __syncthreads(); sh[t] += x; __syncthreads();
    }
    int run = (t == 0) ? 0 : sh[t - 1];
#pragma unroll
    for (int i = 0; i < 4; i++) {
        int idx = base + i;
        run += v[i];
        if (idx < n) g_incl[idx] = run;
    }
    if (t == 255) g_bsum[b] = sh[255];
}
__global__ void k_scan2(int nb) {
    __shared__ int sh[256];
    int t = threadIdx.x;
    int v = (t < nb) ? g_bsum[t] : 0;
    sh[t] = v; __syncthreads();
    for (int off = 1; off < 256; off <<= 1) {
        int x = (t >= off) ? sh[t - off] : 0;
        __syncthreads(); sh[t] += x; __syncthreads();
    }
    g_boff[t] = sh[t] - v;
}
__global__ void k_scan3(int n) {
    int i = blockIdx.x * blockDim.x + threadIdx.x;
    if (i < n) {
        g_rowptr[i + 1] = g_incl[i] + g_boff[i >> 10];
        if (i == 0) g_rowptr[0] = 0;
    }
}
__global__ void k_fill(const int* __restrict__ src, const int* __restrict__ dst, int e) {
    int i = blockIdx.x * blockDim.x + threadIdx.x;
    if (i < e) {
        int d = dst[i];
        int pos = g_rowptr[d] + atomicAdd(&g_fill[d], 1);
        g_csr[pos] = src[i];
    }
}

// ---------------- W split: transposed fp16 hi/lo images Bt[n][k] ----------------
__global__ void k_wsplit(const float* __restrict__ W) {
    int idx = blockIdx.x * blockDim.x + threadIdx.x;   // 3*128*64
    if (idx >= 3 * 128 * 64) return;
    int l  = idx >> 13;
    int r  = idx & 8191;
    int nn = r >> 6;        // output col
    int kk = r & 63;        // k pair
    int k  = 2 * kk;
    float a = W[l * 16384 + k * 128 + nn];
    float b = W[l * 16384 + (k + 1) * 128 + nn];
    uint32_t whi = pack_h2(a, b);
    float2 f = __half22float2(*(__half2*)&whi);
    uint32_t wlo = pack_h2(a - f.x, b - f.y);
    g_wthi[l * 8192 + nn * 64 + kk] = whi;
    g_wtlo[l * 8192 + nn * 64 + kk] = wlo;
}

// ---------------- HMMA GEMM: h(fp16) = (x @ W) * dis[row] ----------------
// CTA: 256 thr (8 warps), tile 128x128, K=128 fully resident.
// A fp16 single image; W fp16 hi/lo 2-pass; fp32 accum in regs; ldmatrix frags.
#define ASTRIDE 68
#define TILE_U32 (128 * ASTRIDE)          // 8704 u32 per image
#define GEMM_SMEM (3 * TILE_U32 * 4)      // 104448 B

__global__ void __launch_bounds__(256, 1)
k_gemm_mma(const void* __restrict__ xin, int fp32in, int layer,
           uint32_t* __restrict__ h, int n) {
    extern __shared__ uint32_t sm[];
    int t = threadIdx.x;
    int wid = t >> 5, lane = t & 31;
    int g = lane >> 2, t4 = lane & 3;     // mma fragment coords
    int warpM = wid & 3;                  // 4 warps along M (32 rows each)
    int warpN = wid >> 2;                 // 2 warps along N (64 cols each)
    int row0 = blockIdx.x * 128;

    // ---- load B images (hi/lo): 128 rows x 16 uint4 each ----
    {
        const uint4* srcH = (const uint4*)(g_wthi + layer * 8192);
        const uint4* srcL = (const uint4*)(g_wtlo + layer * 8192);
        uint32_t* sBhi = sm + TILE_U32;
        uint32_t* sBlo = sm + 2 * TILE_U32;
#pragma unroll
        for (int i = t; i < 2048; i += 256) {
            int r = i >> 4, q = i & 15;
            uint4 vh = srcH[i];
            uint4 vl = srcL[i];
            *(uint4*)(sBhi + r * ASTRIDE + q * 4) = vh;
            *(uint4*)(sBlo + r * ASTRIDE + q * 4) = vl;
        }
    }
    // ---- load A tile: 128 rows x 128 cols ----
    if (fp32in) {
        const float4* X4 = (const float4*)xin;
#pragma unroll
        for (int it = 0; it < 16; it++) {
            int idx = t + it * 256;       // [0, 4096)
            int r = idx >> 5, q = idx & 31;
            int gr = row0 + r;
            float4 v = (gr < n) ? X4[gr * 32 + q] : make_float4(0.f, 0.f, 0.f, 0.f);
            uint32_t w0 = pack_h2(v.x, v.y);
            uint32_t w1 = pack_h2(v.z, v.w);
            *(uint2*)(sm + r * ASTRIDE + 2 * q) = make_uint2(w0, w1);
        }
    } else {
        const uint4* X4 = (const uint4*)xin;   // fp16: 16 uint4 per row
#pragma unroll
        for (int it = 0; it < 8; it++) {
            int idx = t + it * 256;       // [0, 2048)
            int r = idx >> 4, q = idx & 15;
            int gr = row0 + r;
            uint4 v = (gr < n) ? X4[gr * 16 + q] : make_uint4(0u, 0u, 0u, 0u);
            *(uint4*)(sm + r * ASTRIDE + 4 * q) = v;
        }
    }
    __syncthreads();

    // ldmatrix lane-address offsets (bytes, relative to image base)
    int lrow = lane & 7;
    uint32_t aoff = (uint32_t)(((warpM * 32 + lrow + (((lane >> 3) & 1) << 3)) * ASTRIDE
                                + ((lane >> 4) << 2)) * 4);
    uint32_t boff = (uint32_t)(((warpN * 64 + lrow + ((lane >> 4) << 3)) * ASTRIDE
                                + (((lane >> 3) & 1) << 2)) * 4);
    uint32_t smem_base = smem_u32(sm);
    uint32_t abase = smem_base + aoff;
    uint32_t bhib  = smem_base + TILE_U32 * 4u + boff;
    uint32_t blob  = smem_base + TILE_U32 * 8u + boff;

    float d[2][8][4];
#pragma unroll
    for (int mt = 0; mt < 2; mt++)
#pragma unroll
        for (int nt = 0; nt < 8; nt++)
#pragma unroll
            for (int i = 0; i < 4; i++) d[mt][nt][i] = 0.f;

#pragma unroll
    for (int ks = 0; ks < 8; ks++) {
        uint32_t kbyte = (uint32_t)(ks * 32);   // 8 u32 per kstep
        uint32_t a[2][4];
        LDSM_X4(a[0][0], a[0][1], a[0][2], a[0][3], abase + kbyte);
        LDSM_X4(a[1][0], a[1][1], a[1][2], a[1][3], abase + kbyte + 16u * ASTRIDE * 4u);
        uint32_t bh[8][2], bl[8][2];
#pragma unroll
        for (int ntp = 0; ntp < 4; ntp++) {
            uint32_t off = kbyte + (uint32_t)(ntp * 16 * ASTRIDE * 4);
            LDSM_X4(bh[2 * ntp][0], bh[2 * ntp][1], bh[2 * ntp + 1][0], bh[2 * ntp + 1][1],
                    bhib + off);
            LDSM_X4(bl[2 * ntp][0], bl[2 * ntp][1], bl[2 * ntp + 1][0], bl[2 * ntp + 1][1],
                    blob + off);
        }
#pragma unroll
        for (int mt = 0; mt < 2; mt++)
#pragma unroll
            for (int nt = 0; nt < 8; nt++)
                mma_f16(d[mt][nt], a[mt], bh[nt]);
#pragma unroll
        for (int mt = 0; mt < 2; mt++)
#pragma unroll
            for (int nt = 0; nt < 8; nt++)
                mma_f16(d[mt][nt], a[mt], bl[nt]);
    }

    // ---- epilogue: scale by dis[row], store fp16x2 ----
#pragma unroll
    for (int mt = 0; mt < 2; mt++) {
        int r1 = row0 + warpM * 32 + mt * 16 + g;
        int r2 = r1 + 8;
        float s1 = (r1 < n) ? g_dis[r1] : 0.f;
        float s2 = (r2 < n) ? g_dis[r2] : 0.f;
#pragma unroll
        for (int nt = 0; nt < 8; nt++) {
            int cu = warpN * 32 + nt * 4 + t4;   // u32 (half2) column index
            if (r1 < n) h[r1 * 64 + cu] = pack_h2(d[mt][nt][0] * s1, d[mt][nt][1] * s1);
            if (r2 < n) h[r2 * 64 + cu] = pack_h2(d[mt][nt][2] * s2, d[mt][nt][3] * s2);
        }
    }
}

// ---------------- aggregation: warp per node, fp16 gather, fp32 accum ----------------
__device__ __forceinline__ void acc2(float2& a0, float2& a1, uint2 q) {
    float2 f0 = __half22float2(*(__half2*)&q.x);
    float2 f1 = __half22float2(*(__half2*)&q.y);
    a0.x += f0.x; a0.y += f0.y; a1.x += f1.x; a1.y += f1.y;
}

__global__ void __launch_bounds__(256)
k_aggregate(const uint32_t* __restrict__ h, const float* __restrict__ bias,
            float* __restrict__ outf, uint32_t* __restrict__ outh, int final_layer, int n) {
    int warp = (blockIdx.x * blockDim.x + threadIdx.x) >> 5;
    int lane = threadIdx.x & 31;
    if (warp >= n) return;
    int v = warp;

    const uint2* __restrict__ h2 = (const uint2*)h;   // 32 uint2 per row (4 halfs/lane)
    float2 a0 = make_float2(0.f, 0.f), a1 = make_float2(0.f, 0.f);
    float2 c0 = make_float2(0.f, 0.f), c1 = make_float2(0.f, 0.f);
    acc2(a0, a1, h2[v * 32 + lane]);                   // self loop (already *dis[v])

    int s = g_rowptr[v], e = g_rowptr[v + 1];
    for (int base = s; base < e; base += 32) {
        int rem = e - base;
        int m = rem < 32 ? rem : 32;
        int idx = (lane < m) ? g_csr[base + lane] : 0;
        int j = 0;
        for (; j + 4 <= m; j += 4) {
            int u0 = __shfl_sync(0xffffffffu, idx, j);
            int u1 = __shfl_sync(0xffffffffu, idx, j + 1);
            int u2 = __shfl_sync(0xffffffffu, idx, j + 2);
            int u3 = __shfl_sync(0xffffffffu, idx, j + 3);
            uint2 q0 = h2[u0 * 32 + lane];
            uint2 q1 = h2[u1 * 32 + lane];
            uint2 q2 = h2[u2 * 32 + lane];
            uint2 q3 = h2[u3 * 32 + lane];
            acc2(a0, a1, q0);
            acc2(c0, c1, q1);
            acc2(a0, a1, q2);
            acc2(c0, c1, q3);
        }
        for (; j < m; j++) {
            int u = __shfl_sync(0xffffffffu, idx, j);
            acc2(a0, a1, h2[u * 32 + lane]);
        }
    }

    float dv = g_dis[v];
    float4 bb = ((const float4*)bias)[lane];
    float4 o;
    o.x = fmaxf(fmaf(a0.x + c0.x, dv, bb.x), 0.f);
    o.y = fmaxf(fmaf(a0.y + c0.y, dv, bb.y), 0.f);
    o.z = fmaxf(fmaf(a1.x + c1.x, dv, bb.z), 0.f);
    o.w = fmaxf(fmaf(a1.y + c1.y, dv, bb.w), 0.f);
    if (final_layer) {
        ((float4*)outf)[v * 32 + lane] = o;
    } else {
        ((uint2*)outh)[v * 32 + lane] = make_uint2(pack_h2(o.x, o.y), pack_h2(o.z, o.w));
    }
}

// ---------------- launch ----------------
extern "C" void kernel_launch(void* const* d_in, const int* in_sizes, int n_in,
                              void* d_out, int out_size) {
    const float* x    = (const float*)d_in[0];
    const int*   ei   = (const int*)d_in[1];
    const float* W    = (const float*)d_in[2];
    const float* bias = (const float*)d_in[3];
    float* out = (float*)d_out;

    int n = in_sizes[0] / DN;
    int e = in_sizes[1] / 2;
    const int* src = ei;
    const int* dst = ei + e;

    uint32_t *hbuf, *xbuf;
    cudaGetSymbolAddress((void**)&hbuf, g_h);
    cudaGetSymbolAddress((void**)&xbuf, g_x);

    cudaFuncSetAttribute(k_gemm_mma, cudaFuncAttributeMaxDynamicSharedMemorySize, GEMM_SMEM);

    int nb_n = (n + 255) / 256;
    int nb_e = (e + 255) / 256;
    int nchunks = (n + 1023) / 1024;

    // preprocessing: degree + dis + CSR by dst + W split images
    k_init  <<<nb_n, 256>>>(n);
    k_count <<<nb_e, 256>>>(dst, e);
    k_scan1 <<<nchunks, 256>>>(n);
    k_scan2 <<<1, 256>>>(nchunks);
    k_scan3 <<<nb_n, 256>>>(n);
    k_fill  <<<nb_e, 256>>>(src, dst, e);
    k_wsplit<<<(3 * 128 * 64 + 255) / 256, 256>>>(W);

    // 3 GCN layers
    int gemm_blocks = (n + 127) / 128;
    int agg_blocks  = (n * 32 + 255) / 256;
    const void* cur = (const void*)x;
    int fp32in = 1;
    for (int l = 0; l < 3; l++) {
        k_gemm_mma<<<gemm_blocks, 256, GEMM_SMEM>>>(cur, fp32in, l, hbuf, n);
        int fin = (l == 2);
        k_aggregate<<<agg_blocks, 256>>>(hbuf, bias + l * DN, out, xbuf, fin, n);
        cur = (const void*)xbuf;
        fp32in = 0;
    }
}

// round 7
// speedup vs baseline: 2.4682x; 1.0990x over previous
#include <cuda_runtime.h>
#include <cuda_fp16.h>
#include <cstdint>

#define DN 128        // hidden dim
#define NMAX 100000
#define EMAX 1600000

// ---------------- scratch (no allocations allowed) ----------------
__device__ uint32_t g_h[NMAX * 64];      // h_scaled as fp16x2: 64 u32 per row
__device__ uint32_t g_x[NMAX * 64];      // layer output (relu) as fp16x2
__device__ int      g_cnt[NMAX];
__device__ float    g_dis[NMAX];
__device__ int      g_fill[NMAX];
__device__ int      g_csr[EMAX];
__device__ int      g_incl[NMAX];
__device__ int      g_bsum[256];
__device__ int      g_boff[256];
// W^T fp16 image: Bt[n][k] pairs, [3 layers][128 rows][64 u32]
__device__ uint32_t g_wt[3 * 8192];

__device__ __forceinline__ uint32_t pack_h2(float a, float b) {
    __half2 h = __floats2half2_rn(a, b);
    return *(uint32_t*)&h;
}
__device__ __forceinline__ uint32_t smem_u32(const void* p) {
    uint32_t a;
    asm("{ .reg .u64 t; cvta.to.shared.u64 t, %1; cvt.u32.u64 %0, t; }" : "=r"(a) : "l"(p));
    return a;
}
__device__ __forceinline__ void mma_f16(float* d, const uint32_t* a, const uint32_t* b) {
    asm volatile(
        "mma.sync.aligned.m16n8k16.row.col.f32.f16.f16.f32 "
        "{%0,%1,%2,%3}, {%4,%5,%6,%7}, {%8,%9}, {%0,%1,%2,%3};"
        : "+f"(d[0]), "+f"(d[1]), "+f"(d[2]), "+f"(d[3])
        : "r"(a[0]), "r"(a[1]), "r"(a[2]), "r"(a[3]), "r"(b[0]), "r"(b[1]));
}
#define LDSM_X4(r0, r1, r2, r3, addr) \
    asm volatile("ldmatrix.sync.aligned.m8n8.x4.shared.b16 {%0,%1,%2,%3}, [%4];" \
        : "=r"(r0), "=r"(r1), "=r"(r2), "=r"(r3) : "r"(addr))

// ---------------- setup: zero cnt/fill + build W^T fp16 image ----------------
__global__ void k_setup(const float* __restrict__ W, int n) {
    int i = blockIdx.x * blockDim.x + threadIdx.x;
    if (i < n) { g_cnt[i] = 0; g_fill[i] = 0; }
    if (i < 3 * 128 * 64) {
        int l  = i >> 13;
        int r  = i & 8191;
        int nn = r >> 6;        // output col
        int kk = r & 63;        // k pair
        int k  = 2 * kk;
        float a = W[l * 16384 + k * 128 + nn];
        float b = W[l * 16384 + (k + 1) * 128 + nn];
        g_wt[l * 8192 + nn * 64 + kk] = pack_h2(a, b);
    }
}
__global__ void k_count(const int* __restrict__ dst, int e) {
    int i = blockIdx.x * blockDim.x + threadIdx.x;
    if (i < e) atomicAdd(&g_cnt[dst[i]], 1);
}
// scan pass 1 (also computes dis = rsqrt(deg+1))
__global__ void k_scan1(int n) {
    __shared__ int sh[256];
    int t = threadIdx.x, b = blockIdx.x;
    int base = b * 1024 + t * 4;
    int v[4], s = 0;
#pragma unroll
    for (int i = 0; i < 4; i++) {
        int idx = base + i;
        v[i] = (idx < n) ? g_cnt[idx] : 0;
        if (idx < n) g_dis[idx] = rsqrtf((float)(v[i] + 1));
        s += v[i];
    }
    sh[t] = s; __syncthreads();
    for (int off = 1; off < 256; off <<= 1) {
        int x = (t >= off) ? sh[t - off] : 0;
        __syncthreads(); sh[t] += x; __syncthreads();
    }
    int run = (t == 0) ? 0 : sh[t - 1];
#pragma unroll
    for (int i = 0; i < 4; i++) {
        int idx = base + i;
        run += v[i];
        if (idx < n) g_incl[idx] = run;
    }
    if (t == 255) g_bsum[b] = sh[255];
}
__global__ void k_scan2(int nb) {
    __shared__ int sh[256];
    int t = threadIdx.x;
    int v = (t < nb) ? g_bsum[t] : 0;
    sh[t] = v; __syncthreads();
    for (int off = 1; off < 256; off <<= 1) {
        int x = (t >= off) ? sh[t - off] : 0;
        __syncthreads(); sh[t] += x; __syncthreads();
    }
    g_boff[t] = sh[t] - v;
}
// row start for node v (exclusive prefix) = incl[v] + boff - cnt[v]
__device__ __forceinline__ int row_start(int v) {
    return g_incl[v] + g_boff[v >> 10] - g_cnt[v];
}
__global__ void k_fill(const int* __restrict__ src, const int* __restrict__ dst, int e) {
    int i = blockIdx.x * blockDim.x + threadIdx.x;
    if (i < e) {
        int d = dst[i];
        int pos = row_start(d) + atomicAdd(&g_fill[d], 1);
        g_csr[pos] = src[i];
    }
}

// ---------------- HMMA GEMM: h(fp16) = (x @ W) * dis[row] ----------------
// CTA: 256 thr (8 warps), tile 128x128, K=128 fully resident, single fp16 pass.
#define ASTRIDE 68
#define TILE_U32 (128 * ASTRIDE)          // 8704 u32 per image
#define GEMM_SMEM (2 * TILE_U32 * 4)      // 69632 B -> 2 CTAs/SM

__global__ void __launch_bounds__(256, 2)
k_gemm_mma(const void* __restrict__ xin, int fp32in, int layer,
           uint32_t* __restrict__ h, int n) {
    extern __shared__ uint32_t sm[];
    int t = threadIdx.x;
    int wid = t >> 5, lane = t & 31;
    int g = lane >> 2, t4 = lane & 3;     // mma fragment coords
    int warpM = wid & 3;                  // 4 warps along M (32 rows each)
    int warpN = wid >> 2;                 // 2 warps along N (64 cols each)
    int row0 = blockIdx.x * 128;

    // ---- load B image: 128 rows x 16 uint4 ----
    {
        const uint4* srcB = (const uint4*)(g_wt + layer * 8192);
        uint32_t* sB = sm + TILE_U32;
#pragma unroll
        for (int i = t; i < 2048; i += 256) {
            int r = i >> 4, q = i & 15;
            uint4 vb = srcB[i];
            *(uint4*)(sB + r * ASTRIDE + q * 4) = vb;
        }
    }
    // ---- load A tile: 128 rows x 128 cols ----
    if (fp32in) {
        const float4* X4 = (const float4*)xin;
#pragma unroll
        for (int it = 0; it < 16; it++) {
            int idx = t + it * 256;       // [0, 4096)
            int r = idx >> 5, q = idx & 31;
            int gr = row0 + r;
            float4 v = (gr < n) ? X4[gr * 32 + q] : make_float4(0.f, 0.f, 0.f, 0.f);
            uint32_t w0 = pack_h2(v.x, v.y);
            uint32_t w1 = pack_h2(v.z, v.w);
            *(uint2*)(sm + r * ASTRIDE + 2 * q) = make_uint2(w0, w1);
        }
    } else {
        const uint4* X4 = (const uint4*)xin;   // fp16: 16 uint4 per row
#pragma unroll
        for (int it = 0; it < 8; it++) {
            int idx = t + it * 256;       // [0, 2048)
            int r = idx >> 4, q = idx & 15;
            int gr = row0 + r;
            uint4 v = (gr < n) ? X4[gr * 16 + q] : make_uint4(0u, 0u, 0u, 0u);
            *(uint4*)(sm + r * ASTRIDE + 4 * q) = v;
        }
    }
    __syncthreads();

    // ldmatrix lane-address offsets (bytes, relative to image base)
    int lrow = lane & 7;
    uint32_t aoff = (uint32_t)(((warpM * 32 + lrow + (((lane >> 3) & 1) << 3)) * ASTRIDE
                                + ((lane >> 4) << 2)) * 4);
    uint32_t boff = (uint32_t)(((warpN * 64 + lrow + ((lane >> 4) << 3)) * ASTRIDE
                                + (((lane >> 3) & 1) << 2)) * 4);
    uint32_t smem_base = smem_u32(sm);
    uint32_t abase = smem_base + aoff;
    uint32_t bbase = smem_base + TILE_U32 * 4u + boff;

    float d[2][8][4];
#pragma unroll
    for (int mt = 0; mt < 2; mt++)
#pragma unroll
        for (int nt = 0; nt < 8; nt++)
#pragma unroll
            for (int i = 0; i < 4; i++) d[mt][nt][i] = 0.f;

#pragma unroll
    for (int ks = 0; ks < 8; ks++) {
        uint32_t kbyte = (uint32_t)(ks * 32);   // 8 u32 per kstep
        uint32_t a[2][4];
        LDSM_X4(a[0][0], a[0][1], a[0][2], a[0][3], abase + kbyte);
        LDSM_X4(a[1][0], a[1][1], a[1][2], a[1][3], abase + kbyte + 16u * ASTRIDE * 4u);
        uint32_t b[8][2];
#pragma unroll
        for (int ntp = 0; ntp < 4; ntp++) {
            uint32_t off = kbyte + (uint32_t)(ntp * 16 * ASTRIDE * 4);
            LDSM_X4(b[2 * ntp][0], b[2 * ntp][1], b[2 * ntp + 1][0], b[2 * ntp + 1][1],
                    bbase + off);
        }
#pragma unroll
        for (int mt = 0; mt < 2; mt++)
#pragma unroll
            for (int nt = 0; nt < 8; nt++)
                mma_f16(d[mt][nt], a[mt], b[nt]);
    }

    // ---- epilogue: scale by dis[row], store fp16x2 ----
#pragma unroll
    for (int mt = 0; mt < 2; mt++) {
        int r1 = row0 + warpM * 32 + mt * 16 + g;
        int r2 = r1 + 8;
        float s1 = (r1 < n) ? g_dis[r1] : 0.f;
        float s2 = (r2 < n) ? g_dis[r2] : 0.f;
#pragma unroll
        for (int nt = 0; nt < 8; nt++) {
            int cu = warpN * 32 + nt * 4 + t4;   // u32 (half2) column index
            if (r1 < n) h[r1 * 64 + cu] = pack_h2(d[mt][nt][0] * s1, d[mt][nt][1] * s1);
            if (r2 < n) h[r2 * 64 + cu] = pack_h2(d[mt][nt][2] * s2, d[mt][nt][3] * s2);
        }
    }
}

// ---------------- aggregation: warp per node, fp16 gather, fp32 accum ----------------
__device__ __forceinline__ void acc2(float2& a0, float2& a1, uint2 q) {
    float2 f0 = __half22float2(*(__half2*)&q.x);
    float2 f1 = __half22float2(*(__half2*)&q.y);
    a0.x += f0.x; a0.y += f0.y; a1.x += f1.x; a1.y += f1.y;
}

__global__ void __launch_bounds__(256)
k_aggregate(const uint32_t* __restrict__ h, const float* __restrict__ bias,
            float* __restrict__ outf, uint32_t* __restrict__ outh, int final_layer, int n) {
    int warp = (blockIdx.x * blockDim.x + threadIdx.x) >> 5;
    int lane = threadIdx.x & 31;
    if (warp >= n) return;
    int v = warp;

    const uint2* __restrict__ h2 = (const uint2*)h;   // 32 uint2 per row (4 halfs/lane)
    float2 a0 = make_float2(0.f, 0.f), a1 = make_float2(0.f, 0.f);
    float2 c0 = make_float2(0.f, 0.f), c1 = make_float2(0.f, 0.f);
    acc2(a0, a1, h2[v * 32 + lane]);                   // self loop (already *dis[v])

    int cntv = g_cnt[v];
    int s = g_incl[v] + g_boff[v >> 10] - cntv;
    int e = s + cntv;
    for (int base = s; base < e; base += 32) {
        int rem = e - base;
        int m = rem < 32 ? rem : 32;
        int idx = (lane < m) ? g_csr[base + lane] : 0;
        int j = 0;
        for (; j + 4 <= m; j += 4) {
            int u0 = __shfl_sync(0xffffffffu, idx, j);
            int u1 = __shfl_sync(0xffffffffu, idx, j + 1);
            int u2 = __shfl_sync(0xffffffffu, idx, j + 2);
            int u3 = __shfl_sync(0xffffffffu, idx, j + 3);
            uint2 q0 = h2[u0 * 32 + lane];
            uint2 q1 = h2[u1 * 32 + lane];
            uint2 q2 = h2[u2 * 32 + lane];
            uint2 q3 = h2[u3 * 32 + lane];
            acc2(a0, a1, q0);
            acc2(c0, c1, q1);
            acc2(a0, a1, q2);
            acc2(c0, c1, q3);
        }
        for (; j < m; j++) {
            int u = __shfl_sync(0xffffffffu, idx, j);
            acc2(a0, a1, h2[u * 32 + lane]);
        }
    }

    float dv = g_dis[v];
    float4 bb = ((const float4*)bias)[lane];
    float4 o;
    o.x = fmaxf(fmaf(a0.x + c0.x, dv, bb.x), 0.f);
    o.y = fmaxf(fmaf(a0.y + c0.y, dv, bb.y), 0.f);
    o.z = fmaxf(fmaf(a1.x + c1.x, dv, bb.z), 0.f);
    o.w = fmaxf(fmaf(a1.y + c1.y, dv, bb.w), 0.f);
    if (final_layer) {
        ((float4*)outf)[v * 32 + lane] = o;
    } else {
        ((uint2*)outh)[v * 32 + lane] = make_uint2(pack_h2(o.x, o.y), pack_h2(o.z, o.w));
    }
}

// ---------------- launch ----------------
extern "C" void kernel_launch(void* const* d_in, const int* in_sizes, int n_in,
                              void* d_out, int out_size) {
    const float* x    = (const float*)d_in[0];
    const int*   ei   = (const int*)d_in[1];
    const float* W    = (const float*)d_in[2];
    const float* bias = (const float*)d_in[3];
    float* out = (float*)d_out;

    int n = in_sizes[0] / DN;
    int e = in_sizes[1] / 2;
    const int* src = ei;
    const int* dst = ei + e;

    uint32_t *hbuf, *xbuf;
    cudaGetSymbolAddress((void**)&hbuf, g_h);
    cudaGetSymbolAddress((void**)&xbuf, g_x);

    cudaFuncSetAttribute(k_gemm_mma, cudaFuncAttributeMaxDynamicSharedMemorySize, GEMM_SMEM);

    int nb_n = (n + 255) / 256;
    int nb_e = (e + 255) / 256;
    int nchunks = (n + 1023) / 1024;

    // preprocessing: setup(W image + zero) -> count -> scan -> fill
    k_setup <<<nb_n, 256>>>(W, n);
    k_count <<<nb_e, 256>>>(dst, e);
    k_scan1 <<<nchunks, 256>>>(n);
    k_scan2 <<<1, 256>>>(nchunks);
    k_fill  <<<nb_e, 256>>>(src, dst, e);

    // 3 GCN layers
    int gemm_blocks = (n + 127) / 128;
    int agg_blocks  = (n * 32 + 255) / 256;
    const void* cur = (const void*)x;
    int fp32in = 1;
    for (int l = 0; l < 3; l++) {
        k_gemm_mma<<<gemm_blocks, 256, GEMM_SMEM>>>(cur, fp32in, l, hbuf, n);
        int fin = (l == 2);
        k_aggregate<<<agg_blocks, 256>>>(hbuf, bias + l * DN, out, xbuf, fin, n);
        cur = (const void*)xbuf;
        fp32in = 0;
    }
}